// round 3
// baseline (speedup 1.0000x reference)
#include <cuda_runtime.h>

#define NN 10000
#define EE 300000

// ---------------- scratch (__device__ globals, no allocs) ----------------
__device__ __align__(16) float g_h[NN * 32];
__device__ __align__(16) float g_k2[(size_t)EE * 256];
__device__ __align__(16) float g_G[(size_t)256 * NN * 32];   // [c][n][i]
__device__ __align__(16) float g_Bias[NN * 32];
__device__ __align__(16) float g_agg[NN * 32];
__device__ __align__(16) float g_cacc[NN * 3];
__device__ __align__(16) float g_coord[NN * 3];
__device__ float g_cntf[NN];
__device__ int   g_colcnt[NN];
__device__ int   g_rowcnt[NN];
__device__ int   g_cursor[NN];
__device__ int   g_colstart[NN + 1];
__device__ int   g_perm[EE];
__device__ int   g_is64;

// ---------------- edge-index dtype handling ----------------
// edge_index may be int32 (JAX x64 disabled) or int64. Detect at runtime:
// as int64, the high 32-bit word of every element is 0 (ids < 2^31).
__global__ void detect_kernel(const void* __restrict__ ei) {
    const int* w = (const int*)ei;
    int lane = threadIdx.x;
    int hi = w[2 * lane + 1];
    unsigned any = __ballot_sync(0xffffffffu, hi != 0);
    if (lane == 0) g_is64 = (any == 0u) ? 1 : 0;
}

__device__ __forceinline__ int eidx(const void* __restrict__ ei, long long pos, int is64) {
    int v = is64 ? (int)((const long long*)ei)[pos] : ((const int*)ei)[pos];
    // clamp: trap insurance (no-op for valid data)
    return min(max(v, 0), NN - 1);
}

// ---------------- small utility kernels ----------------
__global__ void zero_sort_kernel() {
    int i = blockIdx.x * blockDim.x + threadIdx.x;
    if (i < NN) { g_colcnt[i] = 0; g_rowcnt[i] = 0; g_cursor[i] = 0; }
}

__global__ void zero_acc_kernel() {
    int i = blockIdx.x * blockDim.x + threadIdx.x;
    if (i < NN * 32) g_agg[i] = 0.f;
    if (i < NN * 3)  g_cacc[i] = 0.f;
}

__global__ void coordinit_kernel(const float* __restrict__ ci) {
    int i = blockIdx.x * blockDim.x + threadIdx.x;
    if (i < NN * 3) g_coord[i] = ci[i];
}

__global__ void hist_kernel(const void* __restrict__ ei) {
    int e = blockIdx.x * blockDim.x + threadIdx.x;
    int is64 = g_is64;
    if (e < EE) {
        atomicAdd(&g_rowcnt[eidx(ei, e, is64)], 1);
        atomicAdd(&g_colcnt[eidx(ei, (long long)EE + e, is64)], 1);
    }
}

__global__ void cntf_kernel() {
    int n = blockIdx.x * blockDim.x + threadIdx.x;
    if (n < NN) g_cntf[n] = fmaxf(1.f, (float)g_rowcnt[n]);
}

// one-block exclusive scan over g_colcnt -> g_colstart
__global__ void scan_kernel() {
    const int BPT = 10;  // 1024 * 10 = 10240 >= NN
    int t = threadIdx.x;
    int loc[BPT];
    int s = 0;
#pragma unroll
    for (int j = 0; j < BPT; j++) {
        int b = t * BPT + j;
        int v = (b < NN) ? g_colcnt[b] : 0;
        loc[j] = s; s += v;
    }
    unsigned full = 0xffffffffu;
    int lane = t & 31, wid = t >> 5;
    int v = s;
#pragma unroll
    for (int o = 1; o < 32; o <<= 1) {
        int u = __shfl_up_sync(full, v, o);
        if (lane >= o) v += u;
    }
    __shared__ int wsum[32];
    if (lane == 31) wsum[wid] = v;
    __syncthreads();
    if (wid == 0) {
        int x = wsum[lane];
#pragma unroll
        for (int o = 1; o < 32; o <<= 1) {
            int u = __shfl_up_sync(full, x, o);
            if (lane >= o) x += u;
        }
        wsum[lane] = x;
    }
    __syncthreads();
    int excl = v - s + (wid ? wsum[wid - 1] : 0);
#pragma unroll
    for (int j = 0; j < BPT; j++) {
        int b = t * BPT + j;
        if (b < NN) g_colstart[b] = excl + loc[j];
    }
    if (t == 1023) g_colstart[NN] = wsum[31];
}

__global__ void scatter_kernel(const void* __restrict__ ei) {
    int e = blockIdx.x * blockDim.x + threadIdx.x;
    if (e < EE) {
        int c = eidx(ei, (long long)EE + e, g_is64);
        int p = atomicAdd(&g_cursor[c], 1);
        g_perm[g_colstart[c] + p] = e;
    }
}

// ---------------- model kernels ----------------
// h = x @ fc1_w + fc1_b
__global__ void h0_kernel(const float* __restrict__ x,
                          const float* __restrict__ w, const float* __restrict__ b) {
    int idx = blockIdx.x * blockDim.x + threadIdx.x;
    if (idx >= NN * 32) return;
    int n = idx >> 5, i = idx & 31;
    float acc = b[i];
#pragma unroll
    for (int f = 0; f < 3; f++) acc = fmaf(x[n * 3 + f], w[f * 32 + i], acc);
    g_h[idx] = acc;
}

// Fused edge-kernel MLP: k2 = relu(relu(ea@W1+b1)@W2+b2)
// One block = 16 edges, 256 threads. W2 (128x256, 128KB) streamed through
// SMEM in 32-row chunks; 4x4 register blocking per thread.
#define K2_EPB 16
__global__ void __launch_bounds__(256) k2_kernel(
    const float* __restrict__ ea,
    const float* __restrict__ w1, const float* __restrict__ b1,
    const float* __restrict__ w2, const float* __restrict__ b2)
{
    __shared__ float eas[K2_EPB * 6];
    __shared__ float w1s[6 * 128];
    __shared__ float b1s[128];
    __shared__ float t1s[K2_EPB * 128];
    __shared__ float w2s[32 * 256];

    int e0 = blockIdx.x * K2_EPB;
    int tid = threadIdx.x;

    if (tid < K2_EPB * 6) eas[tid] = ea[e0 * 6 + tid];
    if (tid < 128) b1s[tid] = b1[tid];
    for (int idx = tid; idx < 6 * 128; idx += 256) w1s[idx] = w1[idx];
    __syncthreads();

    // t1 for 16 edges
    for (int idx = tid; idx < K2_EPB * 128; idx += 256) {
        int ee = idx >> 7, j = idx & 127;
        float acc = b1s[j];
#pragma unroll
        for (int f = 0; f < 6; f++) acc = fmaf(eas[ee * 6 + f], w1s[f * 128 + j], acc);
        t1s[idx] = fmaxf(acc, 0.f);
    }
    __syncthreads();

    // GEMM: [16 x 128] @ [128 x 256]
    int c4 = (tid & 63);        // float4-column index (c = c4*4)
    int eb = (tid >> 6) * 4;    // 4 edges per thread
    float acc[4][4];
#pragma unroll
    for (int a = 0; a < 4; a++)
#pragma unroll
        for (int bq = 0; bq < 4; bq++) acc[a][bq] = 0.f;

    const float4* w2g4 = (const float4*)w2;
    float4* w2s4 = (float4*)w2s;
#pragma unroll 1
    for (int ib = 0; ib < 4; ib++) {
        for (int idx = tid; idx < 2048; idx += 256)
            w2s4[idx] = w2g4[ib * 2048 + idx];
        __syncthreads();
#pragma unroll
        for (int i = 0; i < 32; i++) {
            float4 wv = w2s4[i * 64 + c4];
            float t0 = t1s[(eb + 0) * 128 + ib * 32 + i];
            float t1 = t1s[(eb + 1) * 128 + ib * 32 + i];
            float t2 = t1s[(eb + 2) * 128 + ib * 32 + i];
            float t3 = t1s[(eb + 3) * 128 + ib * 32 + i];
            acc[0][0] = fmaf(t0, wv.x, acc[0][0]); acc[0][1] = fmaf(t0, wv.y, acc[0][1]);
            acc[0][2] = fmaf(t0, wv.z, acc[0][2]); acc[0][3] = fmaf(t0, wv.w, acc[0][3]);
            acc[1][0] = fmaf(t1, wv.x, acc[1][0]); acc[1][1] = fmaf(t1, wv.y, acc[1][1]);
            acc[1][2] = fmaf(t1, wv.z, acc[1][2]); acc[1][3] = fmaf(t1, wv.w, acc[1][3]);
            acc[2][0] = fmaf(t2, wv.x, acc[2][0]); acc[2][1] = fmaf(t2, wv.y, acc[2][1]);
            acc[2][2] = fmaf(t2, wv.z, acc[2][2]); acc[2][3] = fmaf(t2, wv.w, acc[2][3]);
            acc[3][0] = fmaf(t3, wv.x, acc[3][0]); acc[3][1] = fmaf(t3, wv.y, acc[3][1]);
            acc[3][2] = fmaf(t3, wv.z, acc[3][2]); acc[3][3] = fmaf(t3, wv.w, acc[3][3]);
        }
        __syncthreads();
    }

    float4 bv = ((const float4*)b2)[c4];
    float4* outp = (float4*)g_k2;
#pragma unroll
    for (int a = 0; a < 4; a++) {
        float4 o;
        o.x = fmaxf(acc[a][0] + bv.x, 0.f);
        o.y = fmaxf(acc[a][1] + bv.y, 0.f);
        o.z = fmaxf(acc[a][2] + bv.z, 0.f);
        o.w = fmaxf(acc[a][3] + bv.w, 0.f);
        outp[(size_t)(e0 + eb + a) * 64 + c4] = o;
    }
}

// G[c][n][i] = sum_j ker3[c*1024 + i*32 + j] * h[n][j]
#define GNT 16   // nodes per block
#define GCL 8    // c-rows per block
__global__ void __launch_bounds__(256) G_kernel(const float* __restrict__ ker3w) {
    __shared__ float hs[GNT * 32];
    int n0 = blockIdx.x * GNT;
    int c0 = blockIdx.y * GCL;
    int tid = threadIdx.x;
    for (int idx = tid; idx < GNT * 32; idx += 256) hs[idx] = g_h[n0 * 32 + idx];
    int cl = tid >> 5, i = tid & 31;
    float kr[32];
    const float4* kp = (const float4*)(ker3w + (size_t)(c0 + cl) * 1024 + i * 32);
#pragma unroll
    for (int q = 0; q < 8; q++) {
        float4 v = kp[q];
        kr[q * 4 + 0] = v.x; kr[q * 4 + 1] = v.y; kr[q * 4 + 2] = v.z; kr[q * 4 + 3] = v.w;
    }
    __syncthreads();
#pragma unroll 2
    for (int nt = 0; nt < GNT; nt++) {
        float acc = 0.f;
#pragma unroll
        for (int j = 0; j < 32; j++) acc = fmaf(kr[j], hs[nt * 32 + j], acc);
        g_G[(size_t)(c0 + cl) * (NN * 32) + (size_t)(n0 + nt) * 32 + i] = acc;
    }
}

// Bias[n][i] = sum_j ker3_b[i*32+j] * h[n][j]
__global__ void bias_kernel(const float* __restrict__ b3) {
    int idx = blockIdx.x * blockDim.x + threadIdx.x;
    if (idx >= NN * 32) return;
    int n = idx >> 5, i = idx & 31;
    float acc = 0.f;
#pragma unroll
    for (int j = 0; j < 32; j++) acc = fmaf(b3[i * 32 + j], g_h[n * 32 + j], acc);
    g_Bias[idx] = acc;
}

// Fully warp-uniform epilogue: shuffles unconditional, only loads/atomics predicated.
__device__ __forceinline__ void edge_epilogue(int e, float m,
    const void* __restrict__ ei, int is64, int lane, float ccol,
    const float* cm1s, const float* cm1bs, const float* cm2s, float cm2b0)
{
    float t = cm1bs[lane];
#pragma unroll
    for (int i = 0; i < 32; i++)
        t = fmaf(__shfl_sync(0xffffffffu, m, i), cm1s[i * 32 + lane], t);
    t = fmaxf(t, 0.f) * cm2s[lane];
#pragma unroll
    for (int off = 16; off; off >>= 1) t += __shfl_xor_sync(0xffffffffu, t, off);
    if (e >= 0) {
        float we = t + cm2b0;
        int r = eidx(ei, e, is64);
        atomicAdd(&g_agg[r * 32 + lane], m);
        if (lane < 3)
            atomicAdd(&g_cacc[r * 3 + lane], (g_coord[r * 3 + lane] - ccol) * we);
    }
}

// One block per destination node n (= col). SMEM-cached G slice reused by all
// incident edges; 4 edges per warp share each LDS.
__global__ void __launch_bounds__(256) edge_kernel(
    const void* __restrict__ ei,
    const float* __restrict__ cm1w, const float* __restrict__ cm1b,
    const float* __restrict__ cm2w, const float* __restrict__ cm2b)
{
    int n = blockIdx.x;
    int cs0 = g_colstart[n];
    int deg = g_colstart[n + 1] - cs0;
    if (deg == 0) return;

    __shared__ float Gs[256 * 32];
    __shared__ float cm1s[32 * 32];
    __shared__ float Bs[32], cm2s[32], cm1bs[32];
    __shared__ float cm2b0s;

    int tid = threadIdx.x;
    int is64 = g_is64;
#pragma unroll
    for (int k = 0; k < 32; k++) {
        int idx = tid + k * 256;
        Gs[idx] = g_G[(size_t)(idx >> 5) * (NN * 32) + n * 32 + (idx & 31)];
    }
    for (int idx = tid; idx < 1024; idx += 256) cm1s[idx] = cm1w[idx];
    if (tid < 32) { Bs[tid] = g_Bias[n * 32 + tid]; cm2s[tid] = cm2w[tid]; cm1bs[tid] = cm1b[tid]; }
    if (tid == 0) cm2b0s = cm2b[0];
    __syncthreads();

    int lane = tid & 31, w = tid >> 5;
    float ccol = (lane < 3) ? g_coord[n * 3 + lane] : 0.f;

    for (int base = 0; base < deg; base += 32) {
        int p = base + w * 4;
        int e0 = (p + 0 < deg) ? g_perm[cs0 + p + 0] : -1;
        int e1 = (p + 1 < deg) ? g_perm[cs0 + p + 1] : -1;
        int e2 = (p + 2 < deg) ? g_perm[cs0 + p + 2] : -1;
        int e3 = (p + 3 < deg) ? g_perm[cs0 + p + 3] : -1;
        float m0 = Bs[lane], m1 = m0, m2 = m0, m3 = m0;
#pragma unroll
        for (int cb = 0; cb < 8; cb++) {
            float kv0 = (e0 >= 0) ? g_k2[(size_t)e0 * 256 + cb * 32 + lane] : 0.f;
            float kv1 = (e1 >= 0) ? g_k2[(size_t)e1 * 256 + cb * 32 + lane] : 0.f;
            float kv2 = (e2 >= 0) ? g_k2[(size_t)e2 * 256 + cb * 32 + lane] : 0.f;
            float kv3 = (e3 >= 0) ? g_k2[(size_t)e3 * 256 + cb * 32 + lane] : 0.f;
#pragma unroll
            for (int t = 0; t < 32; t++) {
                float g = Gs[(cb * 32 + t) * 32 + lane];
                m0 = fmaf(__shfl_sync(0xffffffffu, kv0, t), g, m0);
                m1 = fmaf(__shfl_sync(0xffffffffu, kv1, t), g, m1);
                m2 = fmaf(__shfl_sync(0xffffffffu, kv2, t), g, m2);
                m3 = fmaf(__shfl_sync(0xffffffffu, kv3, t), g, m3);
            }
        }
        edge_epilogue(e0, m0, ei, is64, lane, ccol, cm1s, cm1bs, cm2s, cm2b0s);
        edge_epilogue(e1, m1, ei, is64, lane, ccol, cm1s, cm1bs, cm2s, cm2b0s);
        edge_epilogue(e2, m2, ei, is64, lane, ccol, cm1s, cm1bs, cm2s, cm2b0s);
        edge_epilogue(e3, m3, ei, is64, lane, ccol, cm1s, cm1bs, cm2s, cm2b0s);
    }
}

// h = relu(h + agg/cnt); coord += cacc/cnt
__global__ void node_kernel() {
    int idx = blockIdx.x * blockDim.x + threadIdx.x;
    if (idx >= NN * 32) return;
    int n = idx >> 5, i = idx & 31;
    float cf = g_cntf[n];
    float hv = g_h[idx] + g_agg[idx] / cf;
    g_h[idx] = fmaxf(hv, 0.f);
    if (i < 3) g_coord[n * 3 + i] += g_cacc[n * 3 + i] / cf;
}

// out = relu(h@fc2a+b)@fc2b+b ; also emit coords
__global__ void out_kernel(const float* __restrict__ aw, const float* __restrict__ ab,
                           const float* __restrict__ bw, const float* __restrict__ bb,
                           float* __restrict__ out, int out_size) {
    int n = blockIdx.x * blockDim.x + threadIdx.x;
    if (n >= NN) return;
    float h[32];
    const float4* hp = (const float4*)(g_h + n * 32);
#pragma unroll
    for (int q = 0; q < 8; q++) {
        float4 v = hp[q];
        h[q * 4] = v.x; h[q * 4 + 1] = v.y; h[q * 4 + 2] = v.z; h[q * 4 + 3] = v.w;
    }
    float acc = bb[0];
#pragma unroll 4
    for (int j = 0; j < 64; j++) {
        float t = ab[j];
#pragma unroll
        for (int i = 0; i < 32; i++) t = fmaf(h[i], aw[i * 64 + j], t);
        acc = fmaf(fmaxf(t, 0.f), bw[j], acc);
    }
    out[n] = acc;
#pragma unroll
    for (int d = 0; d < 3; d++) {
        int idx = NN + n * 3 + d;
        if (idx < out_size) out[idx] = g_coord[n * 3 + d];
    }
}

// ---------------- launch ----------------
extern "C" void kernel_launch(void* const* d_in, const int* in_sizes, int n_in,
                              void* d_out, int out_size) {
    const float* x      = (const float*)d_in[0];
    const void*  ei     = d_in[1];
    const float* ea     = (const float*)d_in[2];
    const float* ci     = (const float*)d_in[3];
    const float* fc1w   = (const float*)d_in[4];
    const float* fc1b   = (const float*)d_in[5];
    const float* k1w    = (const float*)d_in[6];
    const float* k1b    = (const float*)d_in[7];
    const float* k2w    = (const float*)d_in[8];
    const float* k2b    = (const float*)d_in[9];
    const float* k3w    = (const float*)d_in[10];
    const float* k3b    = (const float*)d_in[11];
    const float* cm1w   = (const float*)d_in[12];
    const float* cm1b   = (const float*)d_in[13];
    const float* cm2w   = (const float*)d_in[14];
    const float* cm2b   = (const float*)d_in[15];
    const float* fc2aw  = (const float*)d_in[16];
    const float* fc2ab  = (const float*)d_in[17];
    const float* fc2bw  = (const float*)d_in[18];
    const float* fc2bb  = (const float*)d_in[19];
    float* out = (float*)d_out;

    // detect edge_index dtype, then sort edges by col + row counts
    detect_kernel<<<1, 32>>>(ei);
    zero_sort_kernel<<<(NN + 255) / 256, 256>>>();
    hist_kernel<<<(EE + 255) / 256, 256>>>(ei);
    scan_kernel<<<1, 1024>>>();
    cntf_kernel<<<(NN + 255) / 256, 256>>>();
    scatter_kernel<<<(EE + 255) / 256, 256>>>(ei);

    // init node state + edge MLP (layer-invariant)
    coordinit_kernel<<<(NN * 3 + 255) / 256, 256>>>(ci);
    h0_kernel<<<(NN * 32 + 255) / 256, 256>>>(x, fc1w, fc1b);
    k2_kernel<<<EE / K2_EPB, 256>>>(ea, k1w, k1b, k2w, k2b);

    for (int layer = 0; layer < 4; layer++) {
        G_kernel<<<dim3(NN / GNT, 256 / GCL), 256>>>(k3w);
        bias_kernel<<<(NN * 32 + 255) / 256, 256>>>(k3b);
        zero_acc_kernel<<<(NN * 32 + 255) / 256, 256>>>();
        edge_kernel<<<NN, 256>>>(ei, cm1w, cm1b, cm2w, cm2b);
        node_kernel<<<(NN * 32 + 255) / 256, 256>>>();
    }

    out_kernel<<<(NN + 255) / 256, 256>>>(fc2aw, fc2ab, fc2bw, fc2bb, out, out_size);
}

// round 5
// speedup vs baseline: 1.0707x; 1.0707x over previous
#include <cuda_runtime.h>

#define NN 10000
#define EE 300000

// ---------------- scratch (__device__ globals, no allocs) ----------------
__device__ __align__(16) float g_h[NN * 32];
__device__ __align__(16) float g_k2[(size_t)EE * 256];
__device__ __align__(16) float g_G[(size_t)256 * NN * 32];   // [c][n][i]
__device__ __align__(16) float g_Bias[NN * 32];
__device__ __align__(16) float g_agg[NN * 32];
__device__ __align__(16) float g_cacc[NN * 3];
__device__ __align__(16) float g_coord[NN * 3];
__device__ float g_cntf[NN];
__device__ int   g_colcnt[NN];
__device__ int   g_rowcnt[NN];
__device__ int   g_cursor[NN];
__device__ int   g_colstart[NN + 1];
__device__ int   g_perm[EE];
__device__ int   g_is64;

// ---------------- tf32 helpers ----------------
__device__ __forceinline__ unsigned f2tf32(float f) {
    unsigned r;
    asm("cvt.rna.tf32.f32 %0, %1;" : "=r"(r) : "f"(f));
    return r;
}

__device__ __forceinline__ void mma_tf32(float* c, const unsigned* a, const unsigned* b) {
    asm volatile(
        "mma.sync.aligned.m16n8k8.row.col.f32.tf32.tf32.f32 "
        "{%0,%1,%2,%3}, {%4,%5,%6,%7}, {%8,%9}, {%0,%1,%2,%3};"
        : "+f"(c[0]), "+f"(c[1]), "+f"(c[2]), "+f"(c[3])
        : "r"(a[0]), "r"(a[1]), "r"(a[2]), "r"(a[3]), "r"(b[0]), "r"(b[1]));
}

// ---------------- edge-index dtype handling ----------------
__global__ void detect_kernel(const void* __restrict__ ei) {
    const int* w = (const int*)ei;
    int lane = threadIdx.x;
    int hi = w[2 * lane + 1];
    unsigned any = __ballot_sync(0xffffffffu, hi != 0);
    if (lane == 0) g_is64 = (any == 0u) ? 1 : 0;
}

__device__ __forceinline__ int eidx(const void* __restrict__ ei, long long pos, int is64) {
    int v = is64 ? (int)((const long long*)ei)[pos] : ((const int*)ei)[pos];
    return min(max(v, 0), NN - 1);
}

// ---------------- small utility kernels ----------------
__global__ void zero_sort_kernel() {
    int i = blockIdx.x * blockDim.x + threadIdx.x;
    if (i < NN) { g_colcnt[i] = 0; g_rowcnt[i] = 0; g_cursor[i] = 0; }
}

__global__ void zero_acc_kernel() {
    int i = blockIdx.x * blockDim.x + threadIdx.x;
    if (i < NN * 32) g_agg[i] = 0.f;
    if (i < NN * 3)  g_cacc[i] = 0.f;
}

__global__ void coordinit_kernel(const float* __restrict__ ci) {
    int i = blockIdx.x * blockDim.x + threadIdx.x;
    if (i < NN * 3) g_coord[i] = ci[i];
}

__global__ void hist_kernel(const void* __restrict__ ei) {
    int e = blockIdx.x * blockDim.x + threadIdx.x;
    int is64 = g_is64;
    if (e < EE) {
        atomicAdd(&g_rowcnt[eidx(ei, e, is64)], 1);
        atomicAdd(&g_colcnt[eidx(ei, (long long)EE + e, is64)], 1);
    }
}

__global__ void cntf_kernel() {
    int n = blockIdx.x * blockDim.x + threadIdx.x;
    if (n < NN) g_cntf[n] = fmaxf(1.f, (float)g_rowcnt[n]);
}

__global__ void scan_kernel() {
    const int BPT = 10;
    int t = threadIdx.x;
    int loc[BPT];
    int s = 0;
#pragma unroll
    for (int j = 0; j < BPT; j++) {
        int b = t * BPT + j;
        int v = (b < NN) ? g_colcnt[b] : 0;
        loc[j] = s; s += v;
    }
    unsigned full = 0xffffffffu;
    int lane = t & 31, wid = t >> 5;
    int v = s;
#pragma unroll
    for (int o = 1; o < 32; o <<= 1) {
        int u = __shfl_up_sync(full, v, o);
        if (lane >= o) v += u;
    }
    __shared__ int wsum[32];
    if (lane == 31) wsum[wid] = v;
    __syncthreads();
    if (wid == 0) {
        int x = wsum[lane];
#pragma unroll
        for (int o = 1; o < 32; o <<= 1) {
            int u = __shfl_up_sync(full, x, o);
            if (lane >= o) x += u;
        }
        wsum[lane] = x;
    }
    __syncthreads();
    int excl = v - s + (wid ? wsum[wid - 1] : 0);
#pragma unroll
    for (int j = 0; j < BPT; j++) {
        int b = t * BPT + j;
        if (b < NN) g_colstart[b] = excl + loc[j];
    }
    if (t == 1023) g_colstart[NN] = wsum[31];
}

__global__ void scatter_kernel(const void* __restrict__ ei) {
    int e = blockIdx.x * blockDim.x + threadIdx.x;
    if (e < EE) {
        int c = eidx(ei, (long long)EE + e, g_is64);
        int p = atomicAdd(&g_cursor[c], 1);
        g_perm[g_colstart[c] + p] = e;
    }
}

// ---------------- model kernels ----------------
// h = x @ fc1_w + fc1_b
__global__ void h0_kernel(const float* __restrict__ x,
                          const float* __restrict__ w, const float* __restrict__ b) {
    int idx = blockIdx.x * blockDim.x + threadIdx.x;
    if (idx >= NN * 32) return;
    int n = idx >> 5, i = idx & 31;
    float acc = b[i];
#pragma unroll
    for (int f = 0; f < 3; f++) acc = fmaf(x[n * 3 + f], w[f * 32 + i], acc);
    g_h[idx] = acc;
}

// k2 = relu(relu(ea@W1+b1)@W2+b2) via tf32 mma.
// Block tile: 64 edges x 64 cols. t1 computed in-block, staged tf32 in SMEM.
__global__ void __launch_bounds__(256) k2_mma_kernel(
    const float* __restrict__ ea,
    const float* __restrict__ w1, const float* __restrict__ b1,
    const float* __restrict__ w2, const float* __restrict__ b2)
{
    __shared__ unsigned t1s[64 * 132];   // [edge][k] stride 132 (conflict-free A frags)
    __shared__ unsigned w2s[32 * 72];    // [k][n] stride 72 (conflict-free B frags)

    int e0 = blockIdx.x * 64;
    int n0 = blockIdx.y * 64;
    int tid = threadIdx.x;

    // t1 = relu(ea @ W1 + b1), tf32-rounded
    for (int idx = tid; idx < 64 * 128; idx += 256) {
        int el = idx >> 7, j = idx & 127;
        int e = e0 + el;
        float acc = 0.f;
        if (e < EE) {
            acc = b1[j];
#pragma unroll
            for (int f = 0; f < 6; f++) acc = fmaf(ea[e * 6 + f], w1[f * 128 + j], acc);
        }
        t1s[el * 132 + j] = f2tf32(fmaxf(acc, 0.f));
    }

    int w = tid >> 5, lane = tid & 31;
    int g = lane >> 2, tig = lane & 3;
    int wm = w & 1, wn = w >> 1;  // warp tile: m32 (wm), n16 (wn)

    float acc[2][2][4] = {};
    unsigned a[2][4], bf[2][2];

#pragma unroll 1
    for (int kb = 0; kb < 4; kb++) {    // K chunks of 32
        __syncthreads();
        for (int idx = tid; idx < 32 * 64; idx += 256) {
            int kl = idx >> 6, nl = idx & 63;
            w2s[kl * 72 + nl] = f2tf32(w2[(kb * 32 + kl) * 256 + n0 + nl]);
        }
        __syncthreads();
#pragma unroll
        for (int ks = 0; ks < 4; ks++) {
            int kk = kb * 32 + ks * 8;
#pragma unroll
            for (int mi = 0; mi < 2; mi++) {
                int r0 = wm * 32 + mi * 16;
                a[mi][0] = t1s[(r0 + g) * 132 + kk + tig];
                a[mi][1] = t1s[(r0 + g + 8) * 132 + kk + tig];
                a[mi][2] = t1s[(r0 + g) * 132 + kk + tig + 4];
                a[mi][3] = t1s[(r0 + g + 8) * 132 + kk + tig + 4];
            }
#pragma unroll
            for (int ni = 0; ni < 2; ni++) {
                int c0l = wn * 16 + ni * 8;
                bf[ni][0] = w2s[(ks * 8 + tig) * 72 + c0l + g];
                bf[ni][1] = w2s[(ks * 8 + tig + 4) * 72 + c0l + g];
            }
#pragma unroll
            for (int mi = 0; mi < 2; mi++)
#pragma unroll
                for (int ni = 0; ni < 2; ni++)
                    mma_tf32(acc[mi][ni], a[mi], bf[ni]);
        }
    }

#pragma unroll
    for (int mi = 0; mi < 2; mi++) {
        int r = wm * 32 + mi * 16 + g;
#pragma unroll
        for (int ni = 0; ni < 2; ni++) {
            int col = n0 + wn * 16 + ni * 8 + 2 * tig;
            float bz0 = b2[col], bz1 = b2[col + 1];
            int ea_ = e0 + r, eb_ = e0 + r + 8;
            if (ea_ < EE) {
                g_k2[(size_t)ea_ * 256 + col]     = fmaxf(acc[mi][ni][0] + bz0, 0.f);
                g_k2[(size_t)ea_ * 256 + col + 1] = fmaxf(acc[mi][ni][1] + bz1, 0.f);
            }
            if (eb_ < EE) {
                g_k2[(size_t)eb_ * 256 + col]     = fmaxf(acc[mi][ni][2] + bz0, 0.f);
                g_k2[(size_t)eb_ * 256 + col + 1] = fmaxf(acc[mi][ni][3] + bz1, 0.f);
            }
        }
    }
}

// G[c][n][i] = sum_j ker3[c][i*32+j] * h[n][j] via tf32 mma.
// A = h [64 nodes x 32], B[j][(c,i)] = ker3[c][i*32+j], block tile 64 x 64 ci.
__global__ void __launch_bounds__(256) G_mma_kernel(const float* __restrict__ k3w) {
    __shared__ unsigned hs[64 * 36];
    __shared__ unsigned bks[32 * 72];

    int nn0 = blockIdx.x * 64;
    int ci0 = blockIdx.y * 64;
    int tid = threadIdx.x;

    for (int idx = tid; idx < 64 * 32; idx += 256) {
        int nl = idx >> 5, j = idx & 31;
        int n = nn0 + nl;
        hs[nl * 36 + j] = f2tf32(n < NN ? g_h[n * 32 + j] : 0.f);
    }
    for (int idx = tid; idx < 32 * 64; idx += 256) {
        int cil = idx >> 5, j = idx & 31;
        int ci = ci0 + cil;
        bks[j * 72 + cil] = f2tf32(k3w[(size_t)(ci >> 5) * 1024 + (ci & 31) * 32 + j]);
    }
    __syncthreads();

    int w = tid >> 5, lane = tid & 31;
    int g = lane >> 2, tig = lane & 3;
    int wm = w & 1, wn = w >> 1;

    float acc[2][2][4] = {};
    unsigned a[2][4], bf[2][2];

#pragma unroll
    for (int ks = 0; ks < 4; ks++) {
        int kk = ks * 8;
#pragma unroll
        for (int mi = 0; mi < 2; mi++) {
            int r0 = wm * 32 + mi * 16;
            a[mi][0] = hs[(r0 + g) * 36 + kk + tig];
            a[mi][1] = hs[(r0 + g + 8) * 36 + kk + tig];
            a[mi][2] = hs[(r0 + g) * 36 + kk + tig + 4];
            a[mi][3] = hs[(r0 + g + 8) * 36 + kk + tig + 4];
        }
#pragma unroll
        for (int ni = 0; ni < 2; ni++) {
            int c0l = wn * 16 + ni * 8;
            bf[ni][0] = bks[(kk + tig) * 72 + c0l + g];
            bf[ni][1] = bks[(kk + tig + 4) * 72 + c0l + g];
        }
#pragma unroll
        for (int mi = 0; mi < 2; mi++)
#pragma unroll
            for (int ni = 0; ni < 2; ni++)
                mma_tf32(acc[mi][ni], a[mi], bf[ni]);
    }

#pragma unroll
    for (int mi = 0; mi < 2; mi++) {
        int na = nn0 + wm * 32 + mi * 16 + g;
        int nb = na + 8;
#pragma unroll
        for (int ni = 0; ni < 2; ni++) {
            int ci = ci0 + wn * 16 + ni * 8 + 2 * tig;
            size_t o0 = (size_t)(ci >> 5) * (NN * 32) + (ci & 31);
            size_t o1 = (size_t)((ci + 1) >> 5) * (NN * 32) + ((ci + 1) & 31);
            if (na < NN) {
                g_G[o0 + (size_t)na * 32] = acc[mi][ni][0];
                g_G[o1 + (size_t)na * 32] = acc[mi][ni][1];
            }
            if (nb < NN) {
                g_G[o0 + (size_t)nb * 32] = acc[mi][ni][2];
                g_G[o1 + (size_t)nb * 32] = acc[mi][ni][3];
            }
        }
    }
}

// Bias[n][i] = sum_j ker3_b[i*32+j] * h[n][j]  (exact fp32)
__global__ void bias_kernel(const float* __restrict__ b3) {
    int idx = blockIdx.x * blockDim.x + threadIdx.x;
    if (idx >= NN * 32) return;
    int n = idx >> 5, i = idx & 31;
    float acc = 0.f;
#pragma unroll
    for (int j = 0; j < 32; j++) acc = fmaf(b3[i * 32 + j], g_h[n * 32 + j], acc);
    g_Bias[idx] = acc;
}

__device__ __forceinline__ void edge_epilogue(int e, float m,
    const void* __restrict__ ei, int is64, int lane, float ccol,
    const float* cm1s, const float* cm1bs, const float* cm2s, float cm2b0)
{
    float t = cm1bs[lane];
#pragma unroll
    for (int i = 0; i < 32; i++)
        t = fmaf(__shfl_sync(0xffffffffu, m, i), cm1s[i * 32 + lane], t);
    t = fmaxf(t, 0.f) * cm2s[lane];
#pragma unroll
    for (int off = 16; off; off >>= 1) t += __shfl_xor_sync(0xffffffffu, t, off);
    if (e >= 0) {
        float we = t + cm2b0;
        int r = eidx(ei, e, is64);
        atomicAdd(&g_agg[r * 32 + lane], m);
        if (lane < 3)
            atomicAdd(&g_cacc[r * 3 + lane], (g_coord[r * 3 + lane] - ccol) * we);
    }
}

__global__ void __launch_bounds__(256) edge_kernel(
    const void* __restrict__ ei,
    const float* __restrict__ cm1w, const float* __restrict__ cm1b,
    const float* __restrict__ cm2w, const float* __restrict__ cm2b)
{
    int n = blockIdx.x;
    int cs0 = g_colstart[n];
    int deg = g_colstart[n + 1] - cs0;
    if (deg == 0) return;

    __shared__ float Gs[256 * 32];
    __shared__ float cm1s[32 * 32];
    __shared__ float Bs[32], cm2s[32], cm1bs[32];
    __shared__ float cm2b0s;

    int tid = threadIdx.x;
    int is64 = g_is64;
#pragma unroll
    for (int k = 0; k < 32; k++) {
        int idx = tid + k * 256;
        Gs[idx] = g_G[(size_t)(idx >> 5) * (NN * 32) + n * 32 + (idx & 31)];
    }
    for (int idx = tid; idx < 1024; idx += 256) cm1s[idx] = cm1w[idx];
    if (tid < 32) { Bs[tid] = g_Bias[n * 32 + tid]; cm2s[tid] = cm2w[tid]; cm1bs[tid] = cm1b[tid]; }
    if (tid == 0) cm2b0s = cm2b[0];
    __syncthreads();

    int lane = tid & 31, w = tid >> 5;
    float ccol = (lane < 3) ? g_coord[n * 3 + lane] : 0.f;

    for (int base = 0; base < deg; base += 32) {
        int p = base + w * 4;
        int e0 = (p + 0 < deg) ? g_perm[cs0 + p + 0] : -1;
        int e1 = (p + 1 < deg) ? g_perm[cs0 + p + 1] : -1;
        int e2 = (p + 2 < deg) ? g_perm[cs0 + p + 2] : -1;
        int e3 = (p + 3 < deg) ? g_perm[cs0 + p + 3] : -1;
        float m0 = Bs[lane], m1 = m0, m2 = m0, m3 = m0;
#pragma unroll
        for (int cb = 0; cb < 8; cb++) {
            float kv0 = (e0 >= 0) ? g_k2[(size_t)e0 * 256 + cb * 32 + lane] : 0.f;
            float kv1 = (e1 >= 0) ? g_k2[(size_t)e1 * 256 + cb * 32 + lane] : 0.f;
            float kv2 = (e2 >= 0) ? g_k2[(size_t)e2 * 256 + cb * 32 + lane] : 0.f;
            float kv3 = (e3 >= 0) ? g_k2[(size_t)e3 * 256 + cb * 32 + lane] : 0.f;
#pragma unroll
            for (int t = 0; t < 32; t++) {
                float g = Gs[(cb * 32 + t) * 32 + lane];
                m0 = fmaf(__shfl_sync(0xffffffffu, kv0, t), g, m0);
                m1 = fmaf(__shfl_sync(0xffffffffu, kv1, t), g, m1);
                m2 = fmaf(__shfl_sync(0xffffffffu, kv2, t), g, m2);
                m3 = fmaf(__shfl_sync(0xffffffffu, kv3, t), g, m3);
            }
        }
        edge_epilogue(e0, m0, ei, is64, lane, ccol, cm1s, cm1bs, cm2s, cm2b0s);
        edge_epilogue(e1, m1, ei, is64, lane, ccol, cm1s, cm1bs, cm2s, cm2b0s);
        edge_epilogue(e2, m2, ei, is64, lane, ccol, cm1s, cm1bs, cm2s, cm2b0s);
        edge_epilogue(e3, m3, ei, is64, lane, ccol, cm1s, cm1bs, cm2s, cm2b0s);
    }
}

__global__ void node_kernel() {
    int idx = blockIdx.x * blockDim.x + threadIdx.x;
    if (idx >= NN * 32) return;
    int n = idx >> 5, i = idx & 31;
    float cf = g_cntf[n];
    float hv = g_h[idx] + g_agg[idx] / cf;
    g_h[idx] = fmaxf(hv, 0.f);
    if (i < 3) g_coord[n * 3 + i] += g_cacc[n * 3 + i] / cf;
}

__global__ void out_kernel(const float* __restrict__ aw, const float* __restrict__ ab,
                           const float* __restrict__ bw, const float* __restrict__ bb,
                           float* __restrict__ out, int out_size) {
    int n = blockIdx.x * blockDim.x + threadIdx.x;
    if (n >= NN) return;
    float h[32];
    const float4* hp = (const float4*)(g_h + n * 32);
#pragma unroll
    for (int q = 0; q < 8; q++) {
        float4 v = hp[q];
        h[q * 4] = v.x; h[q * 4 + 1] = v.y; h[q * 4 + 2] = v.z; h[q * 4 + 3] = v.w;
    }
    float acc = bb[0];
#pragma unroll 4
    for (int j = 0; j < 64; j++) {
        float t = ab[j];
#pragma unroll
        for (int i = 0; i < 32; i++) t = fmaf(h[i], aw[i * 64 + j], t);
        acc = fmaf(fmaxf(t, 0.f), bw[j], acc);
    }
    out[n] = acc;
#pragma unroll
    for (int d = 0; d < 3; d++) {
        int idx = NN + n * 3 + d;
        if (idx < out_size) out[idx] = g_coord[n * 3 + d];
    }
}

// ---------------- launch ----------------
extern "C" void kernel_launch(void* const* d_in, const int* in_sizes, int n_in,
                              void* d_out, int out_size) {
    const float* x      = (const float*)d_in[0];
    const void*  ei     = d_in[1];
    const float* ea     = (const float*)d_in[2];
    const float* ci     = (const float*)d_in[3];
    const float* fc1w   = (const float*)d_in[4];
    const float* fc1b   = (const float*)d_in[5];
    const float* k1w    = (const float*)d_in[6];
    const float* k1b    = (const float*)d_in[7];
    const float* k2w    = (const float*)d_in[8];
    const float* k2b    = (const float*)d_in[9];
    const float* k3w    = (const float*)d_in[10];
    const float* k3b    = (const float*)d_in[11];
    const float* cm1w   = (const float*)d_in[12];
    const float* cm1b   = (const float*)d_in[13];
    const float* cm2w   = (const float*)d_in[14];
    const float* cm2b   = (const float*)d_in[15];
    const float* fc2aw  = (const float*)d_in[16];
    const float* fc2ab  = (const float*)d_in[17];
    const float* fc2bw  = (const float*)d_in[18];
    const float* fc2bb  = (const float*)d_in[19];
    float* out = (float*)d_out;

    detect_kernel<<<1, 32>>>(ei);
    zero_sort_kernel<<<(NN + 255) / 256, 256>>>();
    hist_kernel<<<(EE + 255) / 256, 256>>>(ei);
    scan_kernel<<<1, 1024>>>();
    cntf_kernel<<<(NN + 255) / 256, 256>>>();
    scatter_kernel<<<(EE + 255) / 256, 256>>>(ei);

    coordinit_kernel<<<(NN * 3 + 255) / 256, 256>>>(ci);
    h0_kernel<<<(NN * 32 + 255) / 256, 256>>>(x, fc1w, fc1b);
    k2_mma_kernel<<<dim3((EE + 63) / 64, 4), 256>>>(ea, k1w, k1b, k2w, k2b);

    for (int layer = 0; layer < 4; layer++) {
        G_mma_kernel<<<dim3((NN + 63) / 64, 128), 256>>>(k3w);
        bias_kernel<<<(NN * 32 + 255) / 256, 256>>>(k3b);
        zero_acc_kernel<<<(NN * 32 + 255) / 256, 256>>>();
        edge_kernel<<<NN, 256>>>(ei, cm1w, cm1b, cm2w, cm2b);
        node_kernel<<<(NN * 32 + 255) / 256, 256>>>();
    }

    out_kernel<<<(NN + 255) / 256, 256>>>(fc2aw, fc2ab, fc2bw, fc2bb, out, out_size);
}